// round 1
// baseline (speedup 1.0000x reference)
#include <cuda_runtime.h>
#include <math_constants.h>

#define DM 2048
#define TS 2048
#define NB 4
#define NHEADS 16
#define HD 128
#define MR (NB * TS)   // 8192 rows

// Scratch (device-global: no allocations allowed in kernel_launch)
__device__ float g_q[MR * DM];
__device__ float g_k[MR * DM];
__device__ float g_v[MR * DM];
__device__ float g_att[MR * DM];

// ---------------------------------------------------------------------------
// GEMM: C[M][N] = A[M][K] * W[N][K]^T + bias[N]
// 128x128 tile, BK=16, 256 threads, 8x8 per thread.
// ---------------------------------------------------------------------------
__global__ __launch_bounds__(256, 2)
void gemm_bias_kernel(const float* __restrict__ A,
                      const float* __restrict__ W,
                      const float* __restrict__ bias,
                      float* __restrict__ C,
                      int M, int N, int K)
{
    __shared__ float As[16][128];
    __shared__ float Bs[16][128];

    const int tid = threadIdx.x;
    const int bm = blockIdx.y * 128;
    const int bn = blockIdx.x * 128;
    const int ty = tid >> 4;        // 0..15
    const int tx = tid & 15;        // 0..15
    const int lr = tid >> 2;        // 0..63
    const int lc = (tid & 3) << 2;  // 0,4,8,12

    const float* Ap = A + (size_t)(bm + lr) * K + lc;
    const float* Wp = W + (size_t)(bn + lr) * K + lc;

    float acc[8][8];
#pragma unroll
    for (int i = 0; i < 8; i++)
#pragma unroll
        for (int j = 0; j < 8; j++) acc[i][j] = 0.f;

    for (int k0 = 0; k0 < K; k0 += 16) {
        float4 a0 = *(const float4*)Ap;
        float4 a1 = *(const float4*)(Ap + (size_t)64 * K);
        float4 b0 = *(const float4*)Wp;
        float4 b1 = *(const float4*)(Wp + (size_t)64 * K);
        Ap += 16; Wp += 16;

        __syncthreads();
        As[lc + 0][lr] = a0.x; As[lc + 1][lr] = a0.y;
        As[lc + 2][lr] = a0.z; As[lc + 3][lr] = a0.w;
        As[lc + 0][lr + 64] = a1.x; As[lc + 1][lr + 64] = a1.y;
        As[lc + 2][lr + 64] = a1.z; As[lc + 3][lr + 64] = a1.w;
        Bs[lc + 0][lr] = b0.x; Bs[lc + 1][lr] = b0.y;
        Bs[lc + 2][lr] = b0.z; Bs[lc + 3][lr] = b0.w;
        Bs[lc + 0][lr + 64] = b1.x; Bs[lc + 1][lr + 64] = b1.y;
        Bs[lc + 2][lr + 64] = b1.z; Bs[lc + 3][lr + 64] = b1.w;
        __syncthreads();

#pragma unroll
        for (int kk = 0; kk < 16; kk++) {
            float4 av0 = *(const float4*)&As[kk][ty * 4];
            float4 av1 = *(const float4*)&As[kk][ty * 4 + 64];
            float4 bv0 = *(const float4*)&Bs[kk][tx * 4];
            float4 bv1 = *(const float4*)&Bs[kk][tx * 4 + 64];
            float a[8]  = {av0.x, av0.y, av0.z, av0.w, av1.x, av1.y, av1.z, av1.w};
            float bb[8] = {bv0.x, bv0.y, bv0.z, bv0.w, bv1.x, bv1.y, bv1.z, bv1.w};
#pragma unroll
            for (int i = 0; i < 8; i++)
#pragma unroll
                for (int j = 0; j < 8; j++)
                    acc[i][j] = fmaf(a[i], bb[j], acc[i][j]);
        }
    }

    float4 bias0 = *(const float4*)&bias[bn + tx * 4];
    float4 bias1 = *(const float4*)&bias[bn + 64 + tx * 4];
#pragma unroll
    for (int i = 0; i < 8; i++) {
        int row = bm + ((i < 4) ? (ty * 4 + i) : (64 + ty * 4 + i - 4));
        float4 o0, o1;
        o0.x = acc[i][0] + bias0.x; o0.y = acc[i][1] + bias0.y;
        o0.z = acc[i][2] + bias0.z; o0.w = acc[i][3] + bias0.w;
        o1.x = acc[i][4] + bias1.x; o1.y = acc[i][5] + bias1.y;
        o1.z = acc[i][6] + bias1.z; o1.w = acc[i][7] + bias1.w;
        *(float4*)&C[(size_t)row * N + bn + tx * 4] = o0;
        *(float4*)&C[(size_t)row * N + bn + 64 + tx * 4] = o1;
    }
}

// ---------------------------------------------------------------------------
// Flash attention (fp32): per (b,h), 64-query x 64-key tiles, hd=128.
// Online softmax; row stats (m,l) in registers (4 rows/thread, 16-lane reduce).
// smem: Qst[128][64], Kst[128][64] (k-major), Vs[64][128], Ps[64][64], mask[64]
// ---------------------------------------------------------------------------
#define FLASH_SMEM_BYTES ((128*64 + 128*64 + 64*128 + 64*64) * 4 + 64 * 4)

__global__ __launch_bounds__(256, 2)
void flash_kernel(const float* __restrict__ Q, const float* __restrict__ K,
                  const float* __restrict__ V, const int* __restrict__ mask,
                  float* __restrict__ O)
{
    extern __shared__ float sm[];
    float* Qst = sm;                  // [128][64] : Qst[k][row]
    float* Kst = Qst + 128 * 64;      // [128][64] : Kst[k][row]
    float* Vs  = Kst + 128 * 64;      // [64][128] : Vs[row][d]
    float* Ps  = Vs + 64 * 128;       // [64][64]
    int*   msk = (int*)(Ps + 64 * 64);

    const int tid = threadIdx.x;
    const int b = blockIdx.x >> 4;
    const int h = blockIdx.x & 15;
    const int q0 = blockIdx.y * 64;
    const size_t base = (size_t)b * TS * DM + (size_t)h * HD;
    const float scale = 0.08838834764831845f;  // 1/sqrt(128)
    const int sy = tid >> 4;   // 0..15 : query rows sy*4..sy*4+3
    const int sx = tid & 15;   // 0..15 : key cols / out cols

    // Load Q tile transposed (rows-per-lane -> conflict-free scatter stores)
    for (int i = tid; i < 64 * 32; i += 256) {
        int r = i & 63, c4 = i >> 6;
        float4 qv = *(const float4*)&Q[base + (size_t)(q0 + r) * DM + c4 * 4];
        int c = c4 * 4;
        Qst[(c + 0) * 64 + r] = qv.x; Qst[(c + 1) * 64 + r] = qv.y;
        Qst[(c + 2) * 64 + r] = qv.z; Qst[(c + 3) * 64 + r] = qv.w;
    }

    float m_run[4], l_run[4];
#pragma unroll
    for (int i = 0; i < 4; i++) { m_run[i] = -CUDART_INF_F; l_run[i] = 0.f; }
    float acc[4][8];
#pragma unroll
    for (int i = 0; i < 4; i++)
#pragma unroll
        for (int j = 0; j < 8; j++) acc[i][j] = 0.f;

    for (int kt = 0; kt < TS / 64; kt++) {
        const int k0 = kt * 64;
        __syncthreads();  // prior iteration's reads of Kst/Vs/Ps done; Q stores done (iter 0)

        // K tile transposed
        for (int i = tid; i < 64 * 32; i += 256) {
            int r = i & 63, c4 = i >> 6;
            float4 kv = *(const float4*)&K[base + (size_t)(k0 + r) * DM + c4 * 4];
            int c = c4 * 4;
            Kst[(c + 0) * 64 + r] = kv.x; Kst[(c + 1) * 64 + r] = kv.y;
            Kst[(c + 2) * 64 + r] = kv.z; Kst[(c + 3) * 64 + r] = kv.w;
        }
        // V tile row-major (coalesced)
        for (int i = tid; i < 64 * 32; i += 256) {
            int r = i >> 5, c4 = i & 31;
            *(float4*)&Vs[r * 128 + c4 * 4] =
                *(const float4*)&V[base + (size_t)(k0 + r) * DM + c4 * 4];
        }
        if (tid < 64) msk[tid] = mask[b * TS + k0 + tid];
        __syncthreads();

        // S = Q . K^T  (4x4 per thread)
        float s[4][4];
#pragma unroll
        for (int i = 0; i < 4; i++)
#pragma unroll
            for (int j = 0; j < 4; j++) s[i][j] = 0.f;

#pragma unroll 4
        for (int kk = 0; kk < 128; kk++) {
            float4 qv = *(const float4*)(Qst + kk * 64 + sy * 4);
            float4 kv = *(const float4*)(Kst + kk * 64 + sx * 4);
            float qa[4] = {qv.x, qv.y, qv.z, qv.w};
            float ka[4] = {kv.x, kv.y, kv.z, kv.w};
#pragma unroll
            for (int i = 0; i < 4; i++)
#pragma unroll
                for (int j = 0; j < 4; j++)
                    s[i][j] = fmaf(qa[i], ka[j], s[i][j]);
        }

        int mloc[4];
#pragma unroll
        for (int j = 0; j < 4; j++) mloc[j] = msk[sx * 4 + j];
#pragma unroll
        for (int i = 0; i < 4; i++)
#pragma unroll
            for (int j = 0; j < 4; j++)
                s[i][j] = (mloc[j] != 0) ? s[i][j] * scale : -CUDART_INF_F;

        // Online softmax per row (reduce over the 16 sx lanes)
#pragma unroll
        for (int i = 0; i < 4; i++) {
            float mx = fmaxf(fmaxf(s[i][0], s[i][1]), fmaxf(s[i][2], s[i][3]));
            mx = fmaxf(mx, __shfl_xor_sync(0xffffffffu, mx, 1));
            mx = fmaxf(mx, __shfl_xor_sync(0xffffffffu, mx, 2));
            mx = fmaxf(mx, __shfl_xor_sync(0xffffffffu, mx, 4));
            mx = fmaxf(mx, __shfl_xor_sync(0xffffffffu, mx, 8));
            float mnew = fmaxf(m_run[i], mx);
            float corr = __expf(m_run[i] - mnew);
            m_run[i] = mnew;
            float4 p;
            p.x = __expf(s[i][0] - mnew);
            p.y = __expf(s[i][1] - mnew);
            p.z = __expf(s[i][2] - mnew);
            p.w = __expf(s[i][3] - mnew);
            *(float4*)&Ps[(sy * 4 + i) * 64 + sx * 4] = p;
            float rs = p.x + p.y + p.z + p.w;
            rs += __shfl_xor_sync(0xffffffffu, rs, 1);
            rs += __shfl_xor_sync(0xffffffffu, rs, 2);
            rs += __shfl_xor_sync(0xffffffffu, rs, 4);
            rs += __shfl_xor_sync(0xffffffffu, rs, 8);
            l_run[i] = l_run[i] * corr + rs;
#pragma unroll
            for (int j = 0; j < 8; j++) acc[i][j] *= corr;
        }
        __syncthreads();

        // O += P . V  (4 rows x 8 cols per thread; cols sx*4 and 64+sx*4)
#pragma unroll 2
        for (int kk2 = 0; kk2 < 64; kk2++) {
            float4 v0 = *(const float4*)&Vs[kk2 * 128 + sx * 4];
            float4 v1 = *(const float4*)&Vs[kk2 * 128 + 64 + sx * 4];
            float vv[8] = {v0.x, v0.y, v0.z, v0.w, v1.x, v1.y, v1.z, v1.w};
            float p[4];
            p[0] = Ps[(sy * 4 + 0) * 64 + kk2];
            p[1] = Ps[(sy * 4 + 1) * 64 + kk2];
            p[2] = Ps[(sy * 4 + 2) * 64 + kk2];
            p[3] = Ps[(sy * 4 + 3) * 64 + kk2];
#pragma unroll
            for (int i = 0; i < 4; i++)
#pragma unroll
                for (int j = 0; j < 8; j++)
                    acc[i][j] = fmaf(p[i], vv[j], acc[i][j]);
        }
    }

    // Normalize and store
#pragma unroll
    for (int i = 0; i < 4; i++) {
        float inv = 1.f / l_run[i];
        float4 o0, o1;
        o0.x = acc[i][0] * inv; o0.y = acc[i][1] * inv;
        o0.z = acc[i][2] * inv; o0.w = acc[i][3] * inv;
        o1.x = acc[i][4] * inv; o1.y = acc[i][5] * inv;
        o1.z = acc[i][6] * inv; o1.w = acc[i][7] * inv;
        size_t row = (size_t)(q0 + sy * 4 + i);
        *(float4*)&O[base + row * DM + sx * 4] = o0;
        *(float4*)&O[base + row * DM + 64 + sx * 4] = o1;
    }
}

// ---------------------------------------------------------------------------
extern "C" void kernel_launch(void* const* d_in, const int* in_sizes, int n_in,
                              void* d_out, int out_size)
{
    const float* x  = (const float*)d_in[0];
    const int* mask = (const int*)d_in[1];
    const float* Wq = (const float*)d_in[2];
    const float* bq = (const float*)d_in[3];
    const float* Wk = (const float*)d_in[4];
    const float* bk = (const float*)d_in[5];
    const float* Wv = (const float*)d_in[6];
    const float* bv = (const float*)d_in[7];
    const float* Wo = (const float*)d_in[8];
    const float* bo = (const float*)d_in[9];
    float* out = (float*)d_out;

    float *q, *k, *v, *att;
    cudaGetSymbolAddress((void**)&q,   g_q);
    cudaGetSymbolAddress((void**)&k,   g_k);
    cudaGetSymbolAddress((void**)&v,   g_v);
    cudaGetSymbolAddress((void**)&att, g_att);

    cudaFuncSetAttribute(flash_kernel,
                         cudaFuncAttributeMaxDynamicSharedMemorySize,
                         FLASH_SMEM_BYTES);

    dim3 ggrid(DM / 128, MR / 128);
    gemm_bias_kernel<<<ggrid, 256>>>(x, Wq, bq, q, MR, DM, DM);
    gemm_bias_kernel<<<ggrid, 256>>>(x, Wk, bk, k, MR, DM, DM);
    gemm_bias_kernel<<<ggrid, 256>>>(x, Wv, bv, v, MR, DM, DM);

    flash_kernel<<<dim3(NB * NHEADS, TS / 64), 256, FLASH_SMEM_BYTES>>>(
        q, k, v, mask, att);

    gemm_bias_kernel<<<ggrid, 256>>>(att, Wo, bo, out, MR, DM, DM);
}

// round 3
// speedup vs baseline: 1.5233x; 1.5233x over previous
#include <cuda_runtime.h>
#include <math_constants.h>
#include <cstdint>

#define DM 2048
#define TS 2048
#define NB 4
#define NHEADS 16
#define HD 128
#define MR (NB * TS)   // 8192 rows

// Scratch (device-global: no allocations allowed in kernel_launch)
__device__ float g_q[MR * DM];
__device__ float g_k[MR * DM];
__device__ float g_v[MR * DM];
__device__ float g_att[MR * DM];
__device__ float g_xr[MR * DM];        // tf32-rounded x
__device__ float g_wr[4 * DM * DM];    // tf32-rounded Wq,Wk,Wv,Wo

// ===========================================================================
// helpers
// ===========================================================================
__device__ __forceinline__ uint32_t smem_u32(const void* p) {
    uint32_t a;
    asm("{ .reg .u64 t; cvta.to.shared.u64 t, %1; cvt.u32.u64 %0, t; }"
        : "=r"(a) : "l"(p));
    return a;
}

__device__ __forceinline__ void cpasync16(uint32_t s, const void* g) {
    asm volatile("cp.async.cg.shared.global [%0], [%1], 16;" :: "r"(s), "l"(g));
}
#define CP_COMMIT() asm volatile("cp.async.commit_group;" ::: "memory")
#define CP_WAIT(n)  asm volatile("cp.async.wait_group %0;" :: "n"(n) : "memory")

__device__ __forceinline__ float round_tf32(float x) {
    uint32_t o;
    asm("cvt.rna.tf32.f32 %0, %1;" : "=r"(o) : "f"(x));
    return __uint_as_float(o);
}

__device__ __forceinline__ void mma_tf32(float* c, const uint32_t* a,
                                         const uint32_t* b) {
    asm volatile(
        "mma.sync.aligned.m16n8k8.row.col.f32.tf32.tf32.f32 "
        "{%0,%1,%2,%3}, {%4,%5,%6,%7}, {%8,%9}, {%0,%1,%2,%3};"
        : "+f"(c[0]), "+f"(c[1]), "+f"(c[2]), "+f"(c[3])
        : "r"(a[0]), "r"(a[1]), "r"(a[2]), "r"(a[3]), "r"(b[0]), "r"(b[1]));
}

// ===========================================================================
// tf32 rounding pre-pass (elementwise, cvt.rna)
// ===========================================================================
__global__ void round_tf32_kernel(const float* __restrict__ in,
                                  float* __restrict__ out, int n4) {
    int i = blockIdx.x * blockDim.x + threadIdx.x;
    int stride = gridDim.x * blockDim.x;
    for (; i < n4; i += stride) {
        float4 v = ((const float4*)in)[i];
        v.x = round_tf32(v.x); v.y = round_tf32(v.y);
        v.z = round_tf32(v.z); v.w = round_tf32(v.w);
        ((float4*)out)[i] = v;
    }
}

// ===========================================================================
// tf32 mma.sync GEMM: C[M][N] = A[M][K] * W[N][K]^T + bias[N]
// Block tile 128x256, BK=16, 4-stage cp.async, 256 threads, warp tile 64x64.
// Smem rows padded to 20 floats (conflict-free fragment loads; 16B aligned).
// ===========================================================================
#define BM 128
#define BN 256
#define BK 16
#define RS 20                       // row stride in floats
#define STAGE_FLOATS (BM * RS + BN * RS)     // 7680
#define GSTAGES 4
#define GEMM_SMEM (GSTAGES * STAGE_FLOATS * 4)  // 122880

__device__ __forceinline__ void load_chunk(const float* __restrict__ A,
                                           const float* __restrict__ W,
                                           float* sm, int slot,
                                           int bm, int bn, int k0, int tid) {
    float* st = sm + slot * STAGE_FLOATS;
    uint32_t sa = smem_u32(st);
#pragma unroll
    for (int r = 0; r < 2; r++) {          // A: 128 rows x 4 x 16B
        int idx = r * 256 + tid;
        int row = idx >> 2, q = idx & 3;
        cpasync16(sa + (row * RS + q * 4) * 4,
                  A + (size_t)(bm + row) * DM + k0 + q * 4);
    }
    uint32_t sb = sa + BM * RS * 4;
#pragma unroll
    for (int r = 0; r < 4; r++) {          // B: 256 rows x 4 x 16B
        int idx = r * 256 + tid;
        int row = idx >> 2, q = idx & 3;
        cpasync16(sb + (row * RS + q * 4) * 4,
                  W + (size_t)(bn + row) * DM + k0 + q * 4);
    }
    CP_COMMIT();
}

__global__ __launch_bounds__(256, 1)
void gemm_tf32_kernel(const float* __restrict__ A,
                      const float* __restrict__ W,
                      const float* __restrict__ bias,
                      float* __restrict__ C)
{
    extern __shared__ float sm[];

    const int tid = threadIdx.x;
    const int bm = blockIdx.y * BM;
    const int bn = blockIdx.x * BN;
    const int wid = tid >> 5;
    const int lane = tid & 31;
    const int wm = wid >> 2;        // 0..1
    const int wn = wid & 3;         // 0..3
    const int g = lane >> 2;        // 0..7
    const int tg = lane & 3;        // 0..3

    float c[4][8][4];
#pragma unroll
    for (int i = 0; i < 4; i++)
#pragma unroll
        for (int j = 0; j < 8; j++)
#pragma unroll
            for (int v = 0; v < 4; v++) c[i][j][v] = 0.f;

    // Prologue: fill 3 stages
#pragma unroll
    for (int s = 0; s < 3; s++)
        load_chunk(A, W, sm, s, bm, bn, s * BK, tid);

    const int NCHUNK = DM / BK;     // 128
    for (int k = 0; k < NCHUNK; k++) {
        CP_WAIT(2);
        __syncthreads();
        if (k + 3 < NCHUNK)
            load_chunk(A, W, sm, (k + 3) & 3, bm, bn, (k + 3) * BK, tid);

        const float* As = sm + (k & 3) * STAGE_FLOATS;
        const float* Bs = As + BM * RS;

#pragma unroll
        for (int kk = 0; kk < BK; kk += 8) {
            uint32_t a[4][4], b[8][2];
#pragma unroll
            for (int i = 0; i < 4; i++) {
                int r0 = (wm * 64 + i * 16 + g) * RS + kk + tg;
                a[i][0] = __float_as_uint(As[r0]);
                a[i][1] = __float_as_uint(As[r0 + 8 * RS]);
                a[i][2] = __float_as_uint(As[r0 + 4]);
                a[i][3] = __float_as_uint(As[r0 + 8 * RS + 4]);
            }
#pragma unroll
            for (int j = 0; j < 8; j++) {
                int rb = (wn * 64 + j * 8 + g) * RS + kk + tg;
                b[j][0] = __float_as_uint(Bs[rb]);
                b[j][1] = __float_as_uint(Bs[rb + 4]);
            }
#pragma unroll
            for (int i = 0; i < 4; i++)
#pragma unroll
                for (int j = 0; j < 8; j++)
                    mma_tf32(c[i][j], a[i], b[j]);
        }
    }

    // Epilogue: c[i][j] -> rows (wm*64+i*16+g, +8), cols (wn*64+j*8+2tg, +1)
#pragma unroll
    for (int j = 0; j < 8; j++) {
        int col = bn + wn * 64 + j * 8 + 2 * tg;
        float b0 = bias[col], b1 = bias[col + 1];
#pragma unroll
        for (int i = 0; i < 4; i++) {
            int row0 = bm + wm * 64 + i * 16 + g;
            float2 v0 = {c[i][j][0] + b0, c[i][j][1] + b1};
            float2 v1 = {c[i][j][2] + b0, c[i][j][3] + b1};
            *(float2*)&C[(size_t)row0 * DM + col] = v0;
            *(float2*)&C[(size_t)(row0 + 8) * DM + col] = v1;
        }
    }
}

// ---------------------------------------------------------------------------
// Flash attention (fp32), unchanged (online softmax, 64x64 tiles)
// ---------------------------------------------------------------------------
#define FLASH_SMEM_BYTES ((128*64 + 128*64 + 64*128 + 64*64) * 4 + 64 * 4)

__global__ __launch_bounds__(256, 2)
void flash_kernel(const float* __restrict__ Q, const float* __restrict__ K,
                  const float* __restrict__ V, const int* __restrict__ mask,
                  float* __restrict__ O)
{
    extern __shared__ float sm[];
    float* Qst = sm;
    float* Kst = Qst + 128 * 64;
    float* Vs  = Kst + 128 * 64;
    float* Ps  = Vs + 64 * 128;
    int*   msk = (int*)(Ps + 64 * 64);

    const int tid = threadIdx.x;
    const int b = blockIdx.x >> 4;
    const int h = blockIdx.x & 15;
    const int q0 = blockIdx.y * 64;
    const size_t base = (size_t)b * TS * DM + (size_t)h * HD;
    const float scale = 0.08838834764831845f;
    const int sy = tid >> 4;
    const int sx = tid & 15;

    for (int i = tid; i < 64 * 32; i += 256) {
        int r = i & 63, c4 = i >> 6;
        float4 qv = *(const float4*)&Q[base + (size_t)(q0 + r) * DM + c4 * 4];
        int c = c4 * 4;
        Qst[(c + 0) * 64 + r] = qv.x; Qst[(c + 1) * 64 + r] = qv.y;
        Qst[(c + 2) * 64 + r] = qv.z; Qst[(c + 3) * 64 + r] = qv.w;
    }

    float m_run[4], l_run[4];
#pragma unroll
    for (int i = 0; i < 4; i++) { m_run[i] = -CUDART_INF_F; l_run[i] = 0.f; }
    float acc[4][8];
#pragma unroll
    for (int i = 0; i < 4; i++)
#pragma unroll
        for (int j = 0; j < 8; j++) acc[i][j] = 0.f;

    for (int kt = 0; kt < TS / 64; kt++) {
        const int k0 = kt * 64;
        __syncthreads();

        for (int i = tid; i < 64 * 32; i += 256) {
            int r = i & 63, c4 = i >> 6;
            float4 kv = *(const float4*)&K[base + (size_t)(k0 + r) * DM + c4 * 4];
            int c = c4 * 4;
            Kst[(c + 0) * 64 + r] = kv.x; Kst[(c + 1) * 64 + r] = kv.y;
            Kst[(c + 2) * 64 + r] = kv.z; Kst[(c + 3) * 64 + r] = kv.w;
        }
        for (int i = tid; i < 64 * 32; i += 256) {
            int r = i >> 5, c4 = i & 31;
            *(float4*)&Vs[r * 128 + c4 * 4] =
                *(const float4*)&V[base + (size_t)(k0 + r) * DM + c4 * 4];
        }
        if (tid < 64) msk[tid] = mask[b * TS + k0 + tid];
        __syncthreads();

        float s[4][4];
#pragma unroll
        for (int i = 0; i < 4; i++)
#pragma unroll
            for (int j = 0; j < 4; j++) s[i][j] = 0.f;

#pragma unroll 4
        for (int kk = 0; kk < 128; kk++) {
            float4 qv = *(const float4*)(Qst + kk * 64 + sy * 4);
            float4 kv = *(const float4*)(Kst + kk * 64 + sx * 4);
            float qa[4] = {qv.x, qv.y, qv.z, qv.w};
            float ka[4] = {kv.x, kv.y, kv.z, kv.w};
#pragma unroll
            for (int i = 0; i < 4; i++)
#pragma unroll
                for (int j = 0; j < 4; j++)
                    s[i][j] = fmaf(qa[i], ka[j], s[i][j]);
        }

        int mloc[4];
#pragma unroll
        for (int j = 0; j < 4; j++) mloc[j] = msk[sx * 4 + j];
#pragma unroll
        for (int i = 0; i < 4; i++)
#pragma unroll
            for (int j = 0; j < 4; j++)
                s[i][j] = (mloc[j] != 0) ? s[i][j] * scale : -CUDART_INF_F;

#pragma unroll
        for (int i = 0; i < 4; i++) {
            float mx = fmaxf(fmaxf(s[i][0], s[i][1]), fmaxf(s[i][2], s[i][3]));
            mx = fmaxf(mx, __shfl_xor_sync(0xffffffffu, mx, 1));
            mx = fmaxf(mx, __shfl_xor_sync(0xffffffffu, mx, 2));
            mx = fmaxf(mx, __shfl_xor_sync(0xffffffffu, mx, 4));
            mx = fmaxf(mx, __shfl_xor_sync(0xffffffffu, mx, 8));
            float mnew = fmaxf(m_run[i], mx);
            float corr = __expf(m_run[i] - mnew);
            m_run[i] = mnew;
            float4 p;
            p.x = __expf(s[i][0] - mnew);
            p.y = __expf(s[i][1] - mnew);
            p.z = __expf(s[i][2] - mnew);
            p.w = __expf(s[i][3] - mnew);
            *(float4*)&Ps[(sy * 4 + i) * 64 + sx * 4] = p;
            float rs = p.x + p.y + p.z + p.w;
            rs += __shfl_xor_sync(0xffffffffu, rs, 1);
            rs += __shfl_xor_sync(0xffffffffu, rs, 2);
            rs += __shfl_xor_sync(0xffffffffu, rs, 4);
            rs += __shfl_xor_sync(0xffffffffu, rs, 8);
            l_run[i] = l_run[i] * corr + rs;
#pragma unroll
            for (int j = 0; j < 8; j++) acc[i][j] *= corr;
        }
        __syncthreads();

#pragma unroll 2
        for (int kk2 = 0; kk2 < 64; kk2++) {
            float4 v0 = *(const float4*)&Vs[kk2 * 128 + sx * 4];
            float4 v1 = *(const float4*)&Vs[kk2 * 128 + 64 + sx * 4];
            float vv[8] = {v0.x, v0.y, v0.z, v0.w, v1.x, v1.y, v1.z, v1.w};
            float p[4];
            p[0] = Ps[(sy * 4 + 0) * 64 + kk2];
            p[1] = Ps[(sy * 4 + 1) * 64 + kk2];
            p[2] = Ps[(sy * 4 + 2) * 64 + kk2];
            p[3] = Ps[(sy * 4 + 3) * 64 + kk2];
#pragma unroll
            for (int i = 0; i < 4; i++)
#pragma unroll
                for (int j = 0; j < 8; j++)
                    acc[i][j] = fmaf(p[i], vv[j], acc[i][j]);
        }
    }

#pragma unroll
    for (int i = 0; i < 4; i++) {
        float inv = 1.f / l_run[i];
        float4 o0, o1;
        o0.x = acc[i][0] * inv; o0.y = acc[i][1] * inv;
        o0.z = acc[i][2] * inv; o0.w = acc[i][3] * inv;
        o1.x = acc[i][4] * inv; o1.y = acc[i][5] * inv;
        o1.z = acc[i][6] * inv; o1.w = acc[i][7] * inv;
        size_t row = (size_t)(q0 + sy * 4 + i);
        *(float4*)&O[base + row * DM + sx * 4] = o0;
        *(float4*)&O[base + row * DM + 64 + sx * 4] = o1;
    }
}

// ---------------------------------------------------------------------------
extern "C" void kernel_launch(void* const* d_in, const int* in_sizes, int n_in,
                              void* d_out, int out_size)
{
    const float* x  = (const float*)d_in[0];
    const int* mask = (const int*)d_in[1];
    const float* Wq = (const float*)d_in[2];
    const float* bq = (const float*)d_in[3];
    const float* Wk = (const float*)d_in[4];
    const float* bk = (const float*)d_in[5];
    const float* Wv = (const float*)d_in[6];
    const float* bv = (const float*)d_in[7];
    const float* Wo = (const float*)d_in[8];
    const float* bo = (const float*)d_in[9];
    float* out = (float*)d_out;

    float *q, *k, *v, *att, *xr, *wr;
    cudaGetSymbolAddress((void**)&q,   g_q);
    cudaGetSymbolAddress((void**)&k,   g_k);
    cudaGetSymbolAddress((void**)&v,   g_v);
    cudaGetSymbolAddress((void**)&att, g_att);
    cudaGetSymbolAddress((void**)&xr,  g_xr);
    cudaGetSymbolAddress((void**)&wr,  g_wr);

    cudaFuncSetAttribute(gemm_tf32_kernel,
                         cudaFuncAttributeMaxDynamicSharedMemorySize, GEMM_SMEM);
    cudaFuncSetAttribute(flash_kernel,
                         cudaFuncAttributeMaxDynamicSharedMemorySize,
                         FLASH_SMEM_BYTES);

    const int NX4 = MR * DM / 4;       // x / att elements / 4
    const int NW4 = DM * DM / 4;       // weight elements / 4

    // tf32 rounding pre-pass (kills truncation bias in HW tf32 mma)
    round_tf32_kernel<<<1024, 256>>>(x,  xr, NX4);
    round_tf32_kernel<<<512,  256>>>(Wq, wr + 0 * DM * DM, NW4);
    round_tf32_kernel<<<512,  256>>>(Wk, wr + 1 * DM * DM, NW4);
    round_tf32_kernel<<<512,  256>>>(Wv, wr + 2 * DM * DM, NW4);
    round_tf32_kernel<<<512,  256>>>(Wo, wr + 3 * DM * DM, NW4);

    dim3 ggrid(DM / BN, MR / BM);  // (8, 64)
    gemm_tf32_kernel<<<ggrid, 256, GEMM_SMEM>>>(xr, wr + 0 * DM * DM, bq, q);
    gemm_tf32_kernel<<<ggrid, 256, GEMM_SMEM>>>(xr, wr + 1 * DM * DM, bk, k);
    gemm_tf32_kernel<<<ggrid, 256, GEMM_SMEM>>>(xr, wr + 2 * DM * DM, bv, v);

    flash_kernel<<<dim3(NB * NHEADS, TS / 64), 256, FLASH_SMEM_BYTES>>>(
        q, k, v, mask, att);

    // round attention output, then final projection
    round_tf32_kernel<<<1024, 256>>>(att, att, NX4);
    gemm_tf32_kernel<<<ggrid, 256, GEMM_SMEM>>>(att, wr + 3 * DM * DM, bo, out);
}

// round 4
// speedup vs baseline: 2.6095x; 1.7131x over previous
#include <cuda_runtime.h>
#include <math_constants.h>
#include <cstdint>

#define DM 2048
#define TS 2048
#define NB 4
#define NHEADS 16
#define HD 128
#define MR (NB * TS)   // 8192 rows

// Scratch (device-global: no allocations allowed in kernel_launch)
__device__ float g_q[MR * DM];
__device__ float g_k[MR * DM];
__device__ float g_v[MR * DM];
__device__ float g_att[MR * DM];
__device__ float g_xr[MR * DM];        // tf32-rounded x
__device__ float g_wr[4 * DM * DM];    // tf32-rounded Wq,Wk,Wv,Wo

// ===========================================================================
// helpers
// ===========================================================================
__device__ __forceinline__ uint32_t smem_u32(const void* p) {
    uint32_t a;
    asm("{ .reg .u64 t; cvta.to.shared.u64 t, %1; cvt.u32.u64 %0, t; }"
        : "=r"(a) : "l"(p));
    return a;
}

__device__ __forceinline__ void cpasync16(uint32_t s, const void* g) {
    asm volatile("cp.async.cg.shared.global [%0], [%1], 16;" :: "r"(s), "l"(g));
}
#define CP_COMMIT() asm volatile("cp.async.commit_group;" ::: "memory")
#define CP_WAIT(n)  asm volatile("cp.async.wait_group %0;" :: "n"(n) : "memory")

__device__ __forceinline__ float round_tf32(float x) {
    uint32_t o;
    asm("cvt.rna.tf32.f32 %0, %1;" : "=r"(o) : "f"(x));
    return __uint_as_float(o);
}

__device__ __forceinline__ void mma_tf32(float* c, const uint32_t* a,
                                         const uint32_t* b) {
    asm volatile(
        "mma.sync.aligned.m16n8k8.row.col.f32.tf32.tf32.f32 "
        "{%0,%1,%2,%3}, {%4,%5,%6,%7}, {%8,%9}, {%0,%1,%2,%3};"
        : "+f"(c[0]), "+f"(c[1]), "+f"(c[2]), "+f"(c[3])
        : "r"(a[0]), "r"(a[1]), "r"(a[2]), "r"(a[3]), "r"(b[0]), "r"(b[1]));
}

// ===========================================================================
// tf32 rounding pre-pass (elementwise, cvt.rna)
// ===========================================================================
__global__ void round_tf32_kernel(const float* __restrict__ in,
                                  float* __restrict__ out, int n4) {
    int i = blockIdx.x * blockDim.x + threadIdx.x;
    int stride = gridDim.x * blockDim.x;
    for (; i < n4; i += stride) {
        float4 v = ((const float4*)in)[i];
        v.x = round_tf32(v.x); v.y = round_tf32(v.y);
        v.z = round_tf32(v.z); v.w = round_tf32(v.w);
        ((float4*)out)[i] = v;
    }
}

// ===========================================================================
// tf32 mma.sync GEMM: C[M][N] = A[M][K] * W[N][K]^T + bias[N]
// Block tile 128x256, BK=16, 4-stage cp.async, 256 threads, warp tile 64x64.
// roundOut: round outputs to tf32 (for q/k/v feeding the tf32 flash kernel).
// ===========================================================================
#define BM 128
#define BN 256
#define BK 16
#define RS 20                       // row stride in floats
#define STAGE_FLOATS (BM * RS + BN * RS)     // 7680
#define GEMM_SMEM (4 * STAGE_FLOATS * 4)     // 122880

__device__ __forceinline__ void load_chunk(const float* __restrict__ A,
                                           const float* __restrict__ W,
                                           float* sm, int slot,
                                           int bm, int bn, int k0, int tid) {
    float* st = sm + slot * STAGE_FLOATS;
    uint32_t sa = smem_u32(st);
#pragma unroll
    for (int r = 0; r < 2; r++) {
        int idx = r * 256 + tid;
        int row = idx >> 2, q = idx & 3;
        cpasync16(sa + (row * RS + q * 4) * 4,
                  A + (size_t)(bm + row) * DM + k0 + q * 4);
    }
    uint32_t sb = sa + BM * RS * 4;
#pragma unroll
    for (int r = 0; r < 4; r++) {
        int idx = r * 256 + tid;
        int row = idx >> 2, q = idx & 3;
        cpasync16(sb + (row * RS + q * 4) * 4,
                  W + (size_t)(bn + row) * DM + k0 + q * 4);
    }
    CP_COMMIT();
}

__global__ __launch_bounds__(256, 1)
void gemm_tf32_kernel(const float* __restrict__ A,
                      const float* __restrict__ W,
                      const float* __restrict__ bias,
                      float* __restrict__ C,
                      int roundOut)
{
    extern __shared__ float sm[];

    const int tid = threadIdx.x;
    const int bm = blockIdx.y * BM;
    const int bn = blockIdx.x * BN;
    const int wid = tid >> 5;
    const int lane = tid & 31;
    const int wm = wid >> 2;
    const int wn = wid & 3;
    const int g = lane >> 2;
    const int tg = lane & 3;

    float c[4][8][4];
#pragma unroll
    for (int i = 0; i < 4; i++)
#pragma unroll
        for (int j = 0; j < 8; j++)
#pragma unroll
            for (int v = 0; v < 4; v++) c[i][j][v] = 0.f;

#pragma unroll
    for (int s = 0; s < 3; s++)
        load_chunk(A, W, sm, s, bm, bn, s * BK, tid);

    const int NCHUNK = DM / BK;
    for (int k = 0; k < NCHUNK; k++) {
        CP_WAIT(2);
        __syncthreads();
        if (k + 3 < NCHUNK)
            load_chunk(A, W, sm, (k + 3) & 3, bm, bn, (k + 3) * BK, tid);

        const float* As = sm + (k & 3) * STAGE_FLOATS;
        const float* Bs = As + BM * RS;

#pragma unroll
        for (int kk = 0; kk < BK; kk += 8) {
            uint32_t a[4][4], b[8][2];
#pragma unroll
            for (int i = 0; i < 4; i++) {
                int r0 = (wm * 64 + i * 16 + g) * RS + kk + tg;
                a[i][0] = __float_as_uint(As[r0]);
                a[i][1] = __float_as_uint(As[r0 + 8 * RS]);
                a[i][2] = __float_as_uint(As[r0 + 4]);
                a[i][3] = __float_as_uint(As[r0 + 8 * RS + 4]);
            }
#pragma unroll
            for (int j = 0; j < 8; j++) {
                int rb = (wn * 64 + j * 8 + g) * RS + kk + tg;
                b[j][0] = __float_as_uint(Bs[rb]);
                b[j][1] = __float_as_uint(Bs[rb + 4]);
            }
#pragma unroll
            for (int i = 0; i < 4; i++)
#pragma unroll
                for (int j = 0; j < 8; j++)
                    mma_tf32(c[i][j], a[i], b[j]);
        }
    }

#pragma unroll
    for (int j = 0; j < 8; j++) {
        int col = bn + wn * 64 + j * 8 + 2 * tg;
        float b0 = bias[col], b1 = bias[col + 1];
#pragma unroll
        for (int i = 0; i < 4; i++) {
            int row0 = bm + wm * 64 + i * 16 + g;
            float2 v0 = {c[i][j][0] + b0, c[i][j][1] + b1};
            float2 v1 = {c[i][j][2] + b0, c[i][j][3] + b1};
            if (roundOut) {
                v0.x = round_tf32(v0.x); v0.y = round_tf32(v0.y);
                v1.x = round_tf32(v1.x); v1.y = round_tf32(v1.y);
            }
            *(float2*)&C[(size_t)row0 * DM + col] = v0;
            *(float2*)&C[(size_t)(row0 + 8) * DM + col] = v1;
        }
    }
}

// ===========================================================================
// Tensor-core flash attention (tf32 mma.sync).
// CTA = 128 queries x hd 128, 8 warps, 16 query rows per warp.
// Key tiles of 64. Q/K row-major stride 132; V^T and P stride 68.
// Inputs q/k/v are already tf32-rounded (GEMM epilogue), so mma truncation
// is exact. P rounded with rna; row-sum uses the same rounded values.
// Output written tf32-rounded (feeds final tf32 GEMM).
// ===========================================================================
#define FQ 128
#define FK 64
#define QSTR 132
#define PSTR 68

#define OFF_Q  0
#define OFF_K  (FQ * QSTR)                    // 16896
#define OFF_VT (OFF_K + FK * QSTR)            // 25344
#define OFF_P  (OFF_VT + HD * PSTR)           // 34048
#define OFF_MS (OFF_P + FQ * PSTR)            // 42752
#define FLASH_SMEM_BYTES ((OFF_MS + 64) * 4)  // 171264

__global__ __launch_bounds__(256, 1)
void flash_tc_kernel(const float* __restrict__ Q, const float* __restrict__ K,
                     const float* __restrict__ V, const int* __restrict__ mask,
                     float* __restrict__ O)
{
    extern __shared__ float sm[];
    float* Qs = sm + OFF_Q;
    float* Ks = sm + OFF_K;
    float* Vt = sm + OFF_VT;
    float* Ps = sm + OFF_P;
    int*   msk = (int*)(sm + OFF_MS);

    const int tid = threadIdx.x;
    const int wid = tid >> 5;
    const int lane = tid & 31;
    const int g = lane >> 2;
    const int tg = lane & 3;
    const int b = blockIdx.x >> 4;
    const int h = blockIdx.x & 15;
    const int q0 = blockIdx.y * FQ;
    const size_t base = (size_t)b * TS * DM + (size_t)h * HD;
    const float scale = 0.08838834764831845f;  // 1/sqrt(128)
    const int qr = wid * 16;

    // Load Q tile [128][128] row-major, stride 132
    for (int i = tid; i < FQ * (HD / 4); i += 256) {
        int r = i >> 5, c4 = i & 31;
        *(float4*)&Qs[r * QSTR + c4 * 4] =
            *(const float4*)&Q[base + (size_t)(q0 + r) * DM + c4 * 4];
    }

    float m0 = -CUDART_INF_F, m1 = -CUDART_INF_F;
    float l0 = 0.f, l1 = 0.f;
    float co[16][4];
#pragma unroll
    for (int j = 0; j < 16; j++)
#pragma unroll
        for (int v = 0; v < 4; v++) co[j][v] = 0.f;

    for (int kt = 0; kt < TS / FK; kt++) {
        const int k0 = kt * FK;
        __syncthreads();   // all warps done reading Ks/Vt (and Qs ready, iter 0)

        // K tile [64][128] row-major stride 132
        for (int i = tid; i < FK * (HD / 4); i += 256) {
            int r = i >> 5, c4 = i & 31;
            *(float4*)&Ks[r * QSTR + c4 * 4] =
                *(const float4*)&K[base + (size_t)(k0 + r) * DM + c4 * 4];
        }
        // V tile transposed: Vt[hd][key], stride 68
        for (int i = tid; i < FK * (HD / 4); i += 256) {
            int r = i & 63, c4 = i >> 6;
            float4 vv = *(const float4*)&V[base + (size_t)(k0 + r) * DM + c4 * 4];
            int c = c4 * 4;
            Vt[(c + 0) * PSTR + r] = vv.x; Vt[(c + 1) * PSTR + r] = vv.y;
            Vt[(c + 2) * PSTR + r] = vv.z; Vt[(c + 3) * PSTR + r] = vv.w;
        }
        if (tid < 64) msk[tid] = mask[b * TS + k0 + tid];
        __syncthreads();

        // S = Q . K^T : per-warp 16 rows x 64 cols
        float cs[8][4];
#pragma unroll
        for (int j = 0; j < 8; j++)
#pragma unroll
            for (int v = 0; v < 4; v++) cs[j][v] = 0.f;

#pragma unroll
        for (int ks = 0; ks < 16; ks++) {
            int kk = ks * 8;
            uint32_t a[4];
            int ra = (qr + g) * QSTR + kk + tg;
            a[0] = __float_as_uint(Qs[ra]);
            a[1] = __float_as_uint(Qs[ra + 8 * QSTR]);
            a[2] = __float_as_uint(Qs[ra + 4]);
            a[3] = __float_as_uint(Qs[ra + 8 * QSTR + 4]);
#pragma unroll
            for (int j = 0; j < 8; j++) {
                uint32_t bb[2];
                int rb = (j * 8 + g) * QSTR + kk + tg;
                bb[0] = __float_as_uint(Ks[rb]);
                bb[1] = __float_as_uint(Ks[rb + 4]);
                mma_tf32(cs[j], a, bb);
            }
        }

        // scale + mask
#pragma unroll
        for (int j = 0; j < 8; j++) {
            int c0 = j * 8 + 2 * tg;
            int mk0 = msk[c0], mk1 = msk[c0 + 1];
            cs[j][0] = mk0 ? cs[j][0] * scale : -CUDART_INF_F;
            cs[j][1] = mk1 ? cs[j][1] * scale : -CUDART_INF_F;
            cs[j][2] = mk0 ? cs[j][2] * scale : -CUDART_INF_F;
            cs[j][3] = mk1 ? cs[j][3] * scale : -CUDART_INF_F;
        }

        // row max (rows qr+g and qr+g+8); reduce over tg lanes (xor 1,2)
        float mx0 = -CUDART_INF_F, mx1 = -CUDART_INF_F;
#pragma unroll
        for (int j = 0; j < 8; j++) {
            mx0 = fmaxf(mx0, fmaxf(cs[j][0], cs[j][1]));
            mx1 = fmaxf(mx1, fmaxf(cs[j][2], cs[j][3]));
        }
        mx0 = fmaxf(mx0, __shfl_xor_sync(0xffffffffu, mx0, 1));
        mx0 = fmaxf(mx0, __shfl_xor_sync(0xffffffffu, mx0, 2));
        mx1 = fmaxf(mx1, __shfl_xor_sync(0xffffffffu, mx1, 1));
        mx1 = fmaxf(mx1, __shfl_xor_sync(0xffffffffu, mx1, 2));

        float mn0 = fmaxf(m0, mx0), mn1 = fmaxf(m1, mx1);
        float corr0 = __expf(m0 - mn0), corr1 = __expf(m1 - mn1);
        m0 = mn0; m1 = mn1;

        // P = exp(s-m), rounded to tf32; l uses the rounded values
        float rs0 = 0.f, rs1 = 0.f;
#pragma unroll
        for (int j = 0; j < 8; j++) {
            float p0 = round_tf32(__expf(cs[j][0] - mn0));
            float p1 = round_tf32(__expf(cs[j][1] - mn0));
            float p2 = round_tf32(__expf(cs[j][2] - mn1));
            float p3 = round_tf32(__expf(cs[j][3] - mn1));
            rs0 += p0 + p1; rs1 += p2 + p3;
            int c0 = j * 8 + 2 * tg;
            *(float2*)&Ps[(qr + g) * PSTR + c0] = make_float2(p0, p1);
            *(float2*)&Ps[(qr + g + 8) * PSTR + c0] = make_float2(p2, p3);
        }
        rs0 += __shfl_xor_sync(0xffffffffu, rs0, 1);
        rs0 += __shfl_xor_sync(0xffffffffu, rs0, 2);
        rs1 += __shfl_xor_sync(0xffffffffu, rs1, 1);
        rs1 += __shfl_xor_sync(0xffffffffu, rs1, 2);
        l0 = l0 * corr0 + rs0;
        l1 = l1 * corr1 + rs1;

        // rescale O accumulators
#pragma unroll
        for (int j = 0; j < 16; j++) {
            co[j][0] *= corr0; co[j][1] *= corr0;
            co[j][2] *= corr1; co[j][3] *= corr1;
        }
        __syncwarp();   // P stores visible to the warp's own lds

        // O += P . V  (A = P rows of this warp, B = Vt)
#pragma unroll
        for (int ks2 = 0; ks2 < 8; ks2++) {
            int kk = ks2 * 8;
            uint32_t a[4];
            int ra = (qr + g) * PSTR + kk + tg;
            a[0] = __float_as_uint(Ps[ra]);
            a[1] = __float_as_uint(Ps[ra + 8 * PSTR]);
            a[2] = __float_as_uint(Ps[ra + 4]);
            a[3] = __float_as_uint(Ps[ra + 8 * PSTR + 4]);
#pragma unroll
            for (int j2 = 0; j2 < 16; j2++) {
                uint32_t bb[2];
                int rb = (j2 * 8 + g) * PSTR + kk + tg;
                bb[0] = __float_as_uint(Vt[rb]);
                bb[1] = __float_as_uint(Vt[rb + 4]);
                mma_tf32(co[j2], a, bb);
            }
        }
        __syncwarp();   // P lds done before next tile's stores
    }

    // Epilogue: normalize, round to tf32, store
    float inv0 = 1.f / l0, inv1 = 1.f / l1;
    size_t r0 = (size_t)(q0 + qr + g);
    size_t r1 = r0 + 8;
#pragma unroll
    for (int j2 = 0; j2 < 16; j2++) {
        int col = j2 * 8 + 2 * tg;
        float2 v0 = {round_tf32(co[j2][0] * inv0), round_tf32(co[j2][1] * inv0)};
        float2 v1 = {round_tf32(co[j2][2] * inv1), round_tf32(co[j2][3] * inv1)};
        *(float2*)&O[base + r0 * DM + col] = v0;
        *(float2*)&O[base + r1 * DM + col] = v1;
    }
}

// ---------------------------------------------------------------------------
extern "C" void kernel_launch(void* const* d_in, const int* in_sizes, int n_in,
                              void* d_out, int out_size)
{
    const float* x  = (const float*)d_in[0];
    const int* mask = (const int*)d_in[1];
    const float* Wq = (const float*)d_in[2];
    const float* bq = (const float*)d_in[3];
    const float* Wk = (const float*)d_in[4];
    const float* bk = (const float*)d_in[5];
    const float* Wv = (const float*)d_in[6];
    const float* bv = (const float*)d_in[7];
    const float* Wo = (const float*)d_in[8];
    const float* bo = (const float*)d_in[9];
    float* out = (float*)d_out;

    float *q, *k, *v, *att, *xr, *wr;
    cudaGetSymbolAddress((void**)&q,   g_q);
    cudaGetSymbolAddress((void**)&k,   g_k);
    cudaGetSymbolAddress((void**)&v,   g_v);
    cudaGetSymbolAddress((void**)&att, g_att);
    cudaGetSymbolAddress((void**)&xr,  g_xr);
    cudaGetSymbolAddress((void**)&wr,  g_wr);

    cudaFuncSetAttribute(gemm_tf32_kernel,
                         cudaFuncAttributeMaxDynamicSharedMemorySize, GEMM_SMEM);
    cudaFuncSetAttribute(flash_tc_kernel,
                         cudaFuncAttributeMaxDynamicSharedMemorySize,
                         FLASH_SMEM_BYTES);

    const int NX4 = MR * DM / 4;
    const int NW4 = DM * DM / 4;

    // tf32 rounding pre-pass (kills truncation bias in HW tf32 mma)
    round_tf32_kernel<<<1024, 256>>>(x,  xr, NX4);
    round_tf32_kernel<<<512,  256>>>(Wq, wr + 0 * DM * DM, NW4);
    round_tf32_kernel<<<512,  256>>>(Wk, wr + 1 * DM * DM, NW4);
    round_tf32_kernel<<<512,  256>>>(Wv, wr + 2 * DM * DM, NW4);
    round_tf32_kernel<<<512,  256>>>(Wo, wr + 3 * DM * DM, NW4);

    dim3 ggrid(DM / BN, MR / BM);  // (8, 64)
    // q/k/v written tf32-rounded (roundOut=1) so flash mma has no trunc bias
    gemm_tf32_kernel<<<ggrid, 256, GEMM_SMEM>>>(xr, wr + 0 * DM * DM, bq, q, 1);
    gemm_tf32_kernel<<<ggrid, 256, GEMM_SMEM>>>(xr, wr + 1 * DM * DM, bk, k, 1);
    gemm_tf32_kernel<<<ggrid, 256, GEMM_SMEM>>>(xr, wr + 2 * DM * DM, bv, v, 1);

    flash_tc_kernel<<<dim3(NB * NHEADS, TS / FQ), 256, FLASH_SMEM_BYTES>>>(
        q, k, v, mask, att);

    gemm_tf32_kernel<<<ggrid, 256, GEMM_SMEM>>>(att, wr + 3 * DM * DM, bo, out, 0);
}

// round 5
// speedup vs baseline: 4.3204x; 1.6556x over previous
#include <cuda_runtime.h>
#include <cuda_fp16.h>
#include <math_constants.h>
#include <cstdint>

#define DM 2048
#define TS 2048
#define NB 4
#define NHEADS 16
#define HD 128
#define MR (NB * TS)   // 8192 rows

// Scratch (device-global: no allocations allowed in kernel_launch)
__device__ __half g_xh[MR * DM];
__device__ __half g_wh[4 * DM * DM];
__device__ __half g_qh[MR * DM];
__device__ __half g_kh[MR * DM];
__device__ __half g_vh[MR * DM];
__device__ __half g_ah[MR * DM];

// ===========================================================================
// helpers
// ===========================================================================
__device__ __forceinline__ uint32_t smem_u32(const void* p) {
    uint32_t a;
    asm("{ .reg .u64 t; cvta.to.shared.u64 t, %1; cvt.u32.u64 %0, t; }"
        : "=r"(a) : "l"(p));
    return a;
}

__device__ __forceinline__ void cpasync16(uint32_t s, const void* g) {
    asm volatile("cp.async.cg.shared.global [%0], [%1], 16;" :: "r"(s), "l"(g));
}
#define CP_COMMIT() asm volatile("cp.async.commit_group;" ::: "memory")
#define CP_WAIT(n)  asm volatile("cp.async.wait_group %0;" :: "n"(n) : "memory")

__device__ __forceinline__ void mma_f16(float* c, const uint32_t* a,
                                        const uint32_t* b) {
    asm volatile(
        "mma.sync.aligned.m16n8k16.row.col.f32.f16.f16.f32 "
        "{%0,%1,%2,%3}, {%4,%5,%6,%7}, {%8,%9}, {%0,%1,%2,%3};"
        : "+f"(c[0]), "+f"(c[1]), "+f"(c[2]), "+f"(c[3])
        : "r"(a[0]), "r"(a[1]), "r"(a[2]), "r"(a[3]), "r"(b[0]), "r"(b[1]));
}

// ===========================================================================
// fp32 -> fp16 conversion (rne)
// ===========================================================================
__global__ void cvt_f2h_kernel(const float* __restrict__ in,
                               __half* __restrict__ out, int n4) {
    int i = blockIdx.x * blockDim.x + threadIdx.x;
    int stride = gridDim.x * blockDim.x;
    for (; i < n4; i += stride) {
        float4 v = ((const float4*)in)[i];
        __half2 h0 = __floats2half2_rn(v.x, v.y);
        __half2 h1 = __floats2half2_rn(v.z, v.w);
        uint2 o = {*(uint32_t*)&h0, *(uint32_t*)&h1};
        ((uint2*)out)[i] = o;
    }
}

// ===========================================================================
// fp16 mma.sync GEMM: C[M][N] = A[M][K] * W[N][K]^T + bias[N]
// Block tile 128x256, K-chunk 32 halves, 4-stage cp.async, 256 threads,
// warp tile 64x64. Smem rows padded to 40 halves (20 words, conflict-free).
// outHalf: write half (for q/k/v/att chains) else float (final output).
// ===========================================================================
#define BM 128
#define BN 256
#define BKH 32
#define RSW 20                                  // row stride in 4B words
#define STAGE_WORDS (BM * RSW + BN * RSW)       // 7680
#define GEMM_SMEM (4 * STAGE_WORDS * 4)         // 122880

__device__ __forceinline__ void load_chunk_h(const __half* __restrict__ A,
                                             const __half* __restrict__ W,
                                             uint32_t base, int slot,
                                             int bm, int bn, int k0, int tid) {
    uint32_t sa = base + slot * STAGE_WORDS * 4;
#pragma unroll
    for (int r = 0; r < 2; r++) {          // A: 128 rows x 4 x 16B
        int idx = r * 256 + tid;
        int row = idx >> 2, q = idx & 3;
        cpasync16(sa + (row * RSW + q * 4) * 4,
                  A + (size_t)(bm + row) * DM + k0 + q * 8);
    }
    uint32_t sb = sa + BM * RSW * 4;
#pragma unroll
    for (int r = 0; r < 4; r++) {          // B: 256 rows x 4 x 16B
        int idx = r * 256 + tid;
        int row = idx >> 2, q = idx & 3;
        cpasync16(sb + (row * RSW + q * 4) * 4,
                  W + (size_t)(bn + row) * DM + k0 + q * 8);
    }
    CP_COMMIT();
}

__global__ __launch_bounds__(256, 1)
void gemm_f16_kernel(const __half* __restrict__ A,
                     const __half* __restrict__ W,
                     const float* __restrict__ bias,
                     void* __restrict__ Cout,
                     int outHalf)
{
    extern __shared__ uint32_t smw[];

    const int tid = threadIdx.x;
    const int bm = blockIdx.y * BM;
    const int bn = blockIdx.x * BN;
    const int wid = tid >> 5;
    const int lane = tid & 31;
    const int wm = wid >> 2;
    const int wn = wid & 3;
    const int g = lane >> 2;
    const int tg = lane & 3;
    uint32_t base = smem_u32(smw);

    float c[4][8][4];
#pragma unroll
    for (int i = 0; i < 4; i++)
#pragma unroll
        for (int j = 0; j < 8; j++)
#pragma unroll
            for (int v = 0; v < 4; v++) c[i][j][v] = 0.f;

#pragma unroll
    for (int s = 0; s < 3; s++)
        load_chunk_h(A, W, base, s, bm, bn, s * BKH, tid);

    const int NCHUNK = DM / BKH;    // 64
    for (int k = 0; k < NCHUNK; k++) {
        CP_WAIT(2);
        __syncthreads();
        if (k + 3 < NCHUNK)
            load_chunk_h(A, W, base, (k + 3) & 3, bm, bn, (k + 3) * BKH, tid);

        const uint32_t* As = smw + (k & 3) * STAGE_WORDS;
        const uint32_t* Bs = As + BM * RSW;

#pragma unroll
        for (int kw = 0; kw < 16; kw += 8) {   // two k16 steps (word offset)
            uint32_t a[4][4], b[8][2];
#pragma unroll
            for (int i = 0; i < 4; i++) {
                int w0 = (wm * 64 + i * 16 + g) * RSW + kw + tg;
                a[i][0] = As[w0];
                a[i][1] = As[w0 + 8 * RSW];
                a[i][2] = As[w0 + 4];
                a[i][3] = As[w0 + 8 * RSW + 4];
            }
#pragma unroll
            for (int j = 0; j < 8; j++) {
                int wb = (wn * 64 + j * 8 + g) * RSW + kw + tg;
                b[j][0] = Bs[wb];
                b[j][1] = Bs[wb + 4];
            }
#pragma unroll
            for (int i = 0; i < 4; i++)
#pragma unroll
                for (int j = 0; j < 8; j++)
                    mma_f16(c[i][j], a[i], b[j]);
        }
    }

    // Epilogue: c[i][j] -> rows (wm*64+i*16+g, +8), cols (wn*64+j*8+2tg, +1)
#pragma unroll
    for (int j = 0; j < 8; j++) {
        int col = bn + wn * 64 + j * 8 + 2 * tg;
        float b0 = bias[col], b1 = bias[col + 1];
#pragma unroll
        for (int i = 0; i < 4; i++) {
            int row0 = bm + wm * 64 + i * 16 + g;
            float v00 = c[i][j][0] + b0, v01 = c[i][j][1] + b1;
            float v10 = c[i][j][2] + b0, v11 = c[i][j][3] + b1;
            if (outHalf) {
                __half* C = (__half*)Cout;
                __half2 h0 = __floats2half2_rn(v00, v01);
                __half2 h1 = __floats2half2_rn(v10, v11);
                *(__half2*)&C[(size_t)row0 * DM + col] = h0;
                *(__half2*)&C[(size_t)(row0 + 8) * DM + col] = h1;
            } else {
                float* C = (float*)Cout;
                *(float2*)&C[(size_t)row0 * DM + col] = make_float2(v00, v01);
                *(float2*)&C[(size_t)(row0 + 8) * DM + col] = make_float2(v10, v11);
            }
        }
    }
}

// ===========================================================================
// Tensor-core flash attention (fp16 mma.sync, fp32 softmax/accum).
// CTA = 128 queries x hd 128, 8 warps, 16 query rows per warp, 64-key tiles.
// Q/K rows padded to 136 halves (68 words); V^T / P padded to 72 halves (36 w).
// P stored rne-rounded to half; l-sum uses the same rounded values.
// ===========================================================================
#define FQ 128
#define FK 64
#define QSW 68     // Q/K row stride in words (136 halves)
#define PSW 36     // P/Vt row stride in words (72 halves)

#define OFF_Q  0
#define OFF_K  (FQ * QSW)                    // 8704
#define OFF_VT (OFF_K + FK * QSW)            // 13056
#define OFF_P  (OFF_VT + HD * PSW)           // 17664
#define OFF_MS (OFF_P + FQ * PSW)            // 22272
#define FLASH_SMEM_BYTES ((OFF_MS + 64) * 4) // 89344

__global__ __launch_bounds__(256, 1)
void flash_f16_kernel(const __half* __restrict__ Q, const __half* __restrict__ K,
                      const __half* __restrict__ V, const int* __restrict__ mask,
                      __half* __restrict__ O)
{
    extern __shared__ uint32_t smw[];
    uint32_t* Qs = smw + OFF_Q;
    uint32_t* Ks = smw + OFF_K;
    uint32_t* Vt = smw + OFF_VT;
    uint32_t* Ps = smw + OFF_P;
    int*      msk = (int*)(smw + OFF_MS);
    __half*   VtH = (__half*)Vt;

    const int tid = threadIdx.x;
    const int wid = tid >> 5;
    const int lane = tid & 31;
    const int g = lane >> 2;
    const int tg = lane & 3;
    const int b = blockIdx.x >> 4;
    const int h = blockIdx.x & 15;
    const int q0 = blockIdx.y * FQ;
    const size_t base = (size_t)b * TS * DM + (size_t)h * HD;
    const float scale = 0.08838834764831845f;  // 1/sqrt(128)
    const int qr = wid * 16;

    // Load Q tile [128][128] halves, row stride 68 words
    for (int i = tid; i < FQ * (HD / 8); i += 256) {
        int r = i >> 4, c8 = i & 15;
        *(uint4*)&Qs[r * QSW + c8 * 4] =
            *(const uint4*)&Q[base + (size_t)(q0 + r) * DM + c8 * 8];
    }

    float m0 = -CUDART_INF_F, m1 = -CUDART_INF_F;
    float l0 = 0.f, l1 = 0.f;
    float co[16][4];
#pragma unroll
    for (int j = 0; j < 16; j++)
#pragma unroll
        for (int v = 0; v < 4; v++) co[j][v] = 0.f;

    for (int kt = 0; kt < TS / FK; kt++) {
        const int k0 = kt * FK;
        __syncthreads();

        // K tile [64][128] halves
        for (int i = tid; i < FK * (HD / 8); i += 256) {
            int r = i >> 4, c8 = i & 15;
            *(uint4*)&Ks[r * QSW + c8 * 4] =
                *(const uint4*)&K[base + (size_t)(k0 + r) * DM + c8 * 8];
        }
        // V tile transposed: VtH[hd][key], 72-half stride
        for (int i = tid; i < FK * (HD / 8); i += 256) {
            int r = i & 63, c8 = i >> 6;
            uint4 vv = *(const uint4*)&V[base + (size_t)(k0 + r) * DM + c8 * 8];
            const __half2* hp = (const __half2*)&vv;
            int c = c8 * 8;
#pragma unroll
            for (int t = 0; t < 4; t++) {
                VtH[(c + 2 * t + 0) * (2 * PSW) + r] = __low2half(hp[t]);
                VtH[(c + 2 * t + 1) * (2 * PSW) + r] = __high2half(hp[t]);
            }
        }
        if (tid < 64) msk[tid] = mask[b * TS + k0 + tid];
        __syncthreads();

        // S = Q . K^T : per-warp 16 rows x 64 cols
        float cs[8][4];
#pragma unroll
        for (int j = 0; j < 8; j++)
#pragma unroll
            for (int v = 0; v < 4; v++) cs[j][v] = 0.f;

#pragma unroll
        for (int ks = 0; ks < 8; ks++) {     // 8 x k16
            int kw = ks * 8;
            uint32_t a[4];
            int ra = (qr + g) * QSW + kw + tg;
            a[0] = Qs[ra];
            a[1] = Qs[ra + 8 * QSW];
            a[2] = Qs[ra + 4];
            a[3] = Qs[ra + 8 * QSW + 4];
#pragma unroll
            for (int j = 0; j < 8; j++) {
                uint32_t bb[2];
                int rb = (j * 8 + g) * QSW + kw + tg;
                bb[0] = Ks[rb];
                bb[1] = Ks[rb + 4];
                mma_f16(cs[j], a, bb);
            }
        }

        // scale + mask
#pragma unroll
        for (int j = 0; j < 8; j++) {
            int c0 = j * 8 + 2 * tg;
            int mk0 = msk[c0], mk1 = msk[c0 + 1];
            cs[j][0] = mk0 ? cs[j][0] * scale : -CUDART_INF_F;
            cs[j][1] = mk1 ? cs[j][1] * scale : -CUDART_INF_F;
            cs[j][2] = mk0 ? cs[j][2] * scale : -CUDART_INF_F;
            cs[j][3] = mk1 ? cs[j][3] * scale : -CUDART_INF_F;
        }

        // row max (rows qr+g, qr+g+8); reduce over tg lanes
        float mx0 = -CUDART_INF_F, mx1 = -CUDART_INF_F;
#pragma unroll
        for (int j = 0; j < 8; j++) {
            mx0 = fmaxf(mx0, fmaxf(cs[j][0], cs[j][1]));
            mx1 = fmaxf(mx1, fmaxf(cs[j][2], cs[j][3]));
        }
        mx0 = fmaxf(mx0, __shfl_xor_sync(0xffffffffu, mx0, 1));
        mx0 = fmaxf(mx0, __shfl_xor_sync(0xffffffffu, mx0, 2));
        mx1 = fmaxf(mx1, __shfl_xor_sync(0xffffffffu, mx1, 1));
        mx1 = fmaxf(mx1, __shfl_xor_sync(0xffffffffu, mx1, 2));

        float mn0 = fmaxf(m0, mx0), mn1 = fmaxf(m1, mx1);
        float corr0 = __expf(m0 - mn0), corr1 = __expf(m1 - mn1);
        m0 = mn0; m1 = mn1;

        // P = exp(s-m) -> half(rne); l uses the rounded values
        float rs0 = 0.f, rs1 = 0.f;
#pragma unroll
        for (int j = 0; j < 8; j++) {
            __half2 h0 = __floats2half2_rn(__expf(cs[j][0] - mn0),
                                           __expf(cs[j][1] - mn0));
            __half2 h1 = __floats2half2_rn(__expf(cs[j][2] - mn1),
                                           __expf(cs[j][3] - mn1));
            float2 f0 = __half22float2(h0);
            float2 f1 = __half22float2(h1);
            rs0 += f0.x + f0.y; rs1 += f1.x + f1.y;
            int wp = j * 4 + tg;
            Ps[(qr + g) * PSW + wp] = *(uint32_t*)&h0;
            Ps[(qr + g + 8) * PSW + wp] = *(uint32_t*)&h1;
        }
        rs0 += __shfl_xor_sync(0xffffffffu, rs0, 1);
        rs0 += __shfl_xor_sync(0xffffffffu, rs0, 2);
        rs1 += __shfl_xor_sync(0xffffffffu, rs1, 1);
        rs1 += __shfl_xor_sync(0xffffffffu, rs1, 2);
        l0 = l0 * corr0 + rs0;
        l1 = l1 * corr1 + rs1;

#pragma unroll
        for (int j = 0; j < 16; j++) {
            co[j][0] *= corr0; co[j][1] *= corr0;
            co[j][2] *= corr1; co[j][3] *= corr1;
        }
        __syncwarp();

        // O += P . V  (A = warp's P rows [16 x 64], B = Vt [128 x 64])
#pragma unroll
        for (int ks2 = 0; ks2 < 4; ks2++) {   // 4 x k16 over 64 keys
            int kw = ks2 * 8;
            uint32_t a[4];
            int ra = (qr + g) * PSW + kw + tg;
            a[0] = Ps[ra];
            a[1] = Ps[ra + 8 * PSW];
            a[2] = Ps[ra + 4];
            a[3] = Ps[ra + 8 * PSW + 4];
#pragma unroll
            for (int j2 = 0; j2 < 16; j2++) {
                uint32_t bb[2];
                int rb = (j2 * 8 + g) * PSW + kw + tg;
                bb[0] = Vt[rb];
                bb[1] = Vt[rb + 4];
                mma_f16(co[j2], a, bb);
            }
        }
        __syncwarp();
    }

    // Epilogue: normalize, store half
    float inv0 = 1.f / l0, inv1 = 1.f / l1;
    size_t r0 = (size_t)(q0 + qr + g);
    size_t r1 = r0 + 8;
#pragma unroll
    for (int j2 = 0; j2 < 16; j2++) {
        int col = j2 * 8 + 2 * tg;
        __half2 h0 = __floats2half2_rn(co[j2][0] * inv0, co[j2][1] * inv0);
        __half2 h1 = __floats2half2_rn(co[j2][2] * inv1, co[j2][3] * inv1);
        *(__half2*)&O[base + r0 * DM + col] = h0;
        *(__half2*)&O[base + r1 * DM + col] = h1;
    }
}

// ---------------------------------------------------------------------------
extern "C" void kernel_launch(void* const* d_in, const int* in_sizes, int n_in,
                              void* d_out, int out_size)
{
    const float* x  = (const float*)d_in[0];
    const int* mask = (const int*)d_in[1];
    const float* Wq = (const float*)d_in[2];
    const float* bq = (const float*)d_in[3];
    const float* Wk = (const float*)d_in[4];
    const float* bk = (const float*)d_in[5];
    const float* Wv = (const float*)d_in[6];
    const float* bv = (const float*)d_in[7];
    const float* Wo = (const float*)d_in[8];
    const float* bo = (const float*)d_in[9];
    float* out = (float*)d_out;

    __half *xh, *wh, *qh, *kh, *vh, *ah;
    cudaGetSymbolAddress((void**)&xh, g_xh);
    cudaGetSymbolAddress((void**)&wh, g_wh);
    cudaGetSymbolAddress((void**)&qh, g_qh);
    cudaGetSymbolAddress((void**)&kh, g_kh);
    cudaGetSymbolAddress((void**)&vh, g_vh);
    cudaGetSymbolAddress((void**)&ah, g_ah);

    cudaFuncSetAttribute(gemm_f16_kernel,
                         cudaFuncAttributeMaxDynamicSharedMemorySize, GEMM_SMEM);
    cudaFuncSetAttribute(flash_f16_kernel,
                         cudaFuncAttributeMaxDynamicSharedMemorySize,
                         FLASH_SMEM_BYTES);

    const int NX4 = MR * DM / 4;
    const int NW4 = DM * DM / 4;

    // fp32 -> fp16 conversion (rne)
    cvt_f2h_kernel<<<1024, 256>>>(x,  xh, NX4);
    cvt_f2h_kernel<<<512,  256>>>(Wq, wh + 0 * (size_t)DM * DM, NW4);
    cvt_f2h_kernel<<<512,  256>>>(Wk, wh + 1 * (size_t)DM * DM, NW4);
    cvt_f2h_kernel<<<512,  256>>>(Wv, wh + 2 * (size_t)DM * DM, NW4);
    cvt_f2h_kernel<<<512,  256>>>(Wo, wh + 3 * (size_t)DM * DM, NW4);

    dim3 ggrid(DM / BN, MR / BM);  // (8, 64)
    gemm_f16_kernel<<<ggrid, 256, GEMM_SMEM>>>(xh, wh + 0 * (size_t)DM * DM, bq, qh, 1);
    gemm_f16_kernel<<<ggrid, 256, GEMM_SMEM>>>(xh, wh + 1 * (size_t)DM * DM, bk, kh, 1);
    gemm_f16_kernel<<<ggrid, 256, GEMM_SMEM>>>(xh, wh + 2 * (size_t)DM * DM, bv, vh, 1);

    flash_f16_kernel<<<dim3(NB * NHEADS, TS / FQ), 256, FLASH_SMEM_BYTES>>>(
        qh, kh, vh, mask, ah);

    gemm_f16_kernel<<<ggrid, 256, GEMM_SMEM>>>(ah, wh + 3 * (size_t)DM * DM, bo, out, 0);
}

// round 6
// speedup vs baseline: 4.7789x; 1.1061x over previous
#include <cuda_runtime.h>
#include <cuda_fp16.h>
#include <math_constants.h>
#include <cstdint>

#define DM 2048
#define TS 2048
#define NB 4
#define NHEADS 16
#define HD 128
#define MR (NB * TS)   // 8192 rows
#define NQKV (3 * DM)  // 6144

// Scratch (device-global: no allocations allowed in kernel_launch)
__device__ __half g_xh[MR * DM];
__device__ __half g_wh[4 * DM * DM];
__device__ __half g_qh[MR * DM];
__device__ __half g_kh[MR * DM];
__device__ __half g_vh[MR * DM];
__device__ __half g_ah[MR * DM];
__device__ float  g_bias3[NQKV];

// ===========================================================================
// helpers
// ===========================================================================
__device__ __forceinline__ uint32_t smem_u32(const void* p) {
    uint32_t a;
    asm("{ .reg .u64 t; cvta.to.shared.u64 t, %1; cvt.u32.u64 %0, t; }"
        : "=r"(a) : "l"(p));
    return a;
}

__device__ __forceinline__ void cpasync16(uint32_t s, const void* g) {
    asm volatile("cp.async.cg.shared.global [%0], [%1], 16;" :: "r"(s), "l"(g));
}
#define CP_COMMIT() asm volatile("cp.async.commit_group;" ::: "memory")
#define CP_WAIT(n)  asm volatile("cp.async.wait_group %0;" :: "n"(n) : "memory")

__device__ __forceinline__ void mma_f16(float* c, const uint32_t* a,
                                        const uint32_t* b) {
    asm volatile(
        "mma.sync.aligned.m16n8k16.row.col.f32.f16.f16.f32 "
        "{%0,%1,%2,%3}, {%4,%5,%6,%7}, {%8,%9}, {%0,%1,%2,%3};"
        : "+f"(c[0]), "+f"(c[1]), "+f"(c[2]), "+f"(c[3])
        : "r"(a[0]), "r"(a[1]), "r"(a[2]), "r"(a[3]), "r"(b[0]), "r"(b[1]));
}

// ===========================================================================
// fp32 -> fp16 conversion (rne); bias concat
// ===========================================================================
__global__ void cvt_f2h_kernel(const float* __restrict__ in,
                               __half* __restrict__ out, int n4) {
    int i = blockIdx.x * blockDim.x + threadIdx.x;
    int stride = gridDim.x * blockDim.x;
    for (; i < n4; i += stride) {
        float4 v = ((const float4*)in)[i];
        __half2 h0 = __floats2half2_rn(v.x, v.y);
        __half2 h1 = __floats2half2_rn(v.z, v.w);
        uint2 o = {*(uint32_t*)&h0, *(uint32_t*)&h1};
        ((uint2*)out)[i] = o;
    }
}

__global__ void pack_bias_kernel(const float* __restrict__ a,
                                 const float* __restrict__ b,
                                 const float* __restrict__ c,
                                 float* __restrict__ o) {
    int i = blockIdx.x * blockDim.x + threadIdx.x;
    if (i < DM) {
        o[i] = a[i];
        o[i + DM] = b[i];
        o[i + 2 * DM] = c[i];
    }
}

// ===========================================================================
// fp16 mma.sync GEMM: C[M][col] = A[M][K] * W[col][K]^T + bias[col]
// Block tile 128x256, K-chunk 64 halves, 4-stage cp.async, 256 threads,
// warp tile 64x64. Rows padded to 72 halves (36 words) - conflict-free.
// N can span multiple 2048-col outputs (fused QKV): epilogue selects
// output pointer by (bn >> 11); col_local = col & 2047.
// outHalf: write half (QKV chain) else float (final output, C0 only).
// ===========================================================================
#define BM 128
#define BN 256
#define BKH 64
#define RSW 36                                  // row stride in 4B words
#define STAGE_WORDS (BM * RSW + BN * RSW)       // 13824
#define GEMM_SMEM (4 * STAGE_WORDS * 4)         // 221184

__device__ __forceinline__ void load_chunk_h(const __half* __restrict__ A,
                                             const __half* __restrict__ W,
                                             uint32_t base, int slot,
                                             int bm, int bn, int k0, int tid) {
    uint32_t sa = base + slot * STAGE_WORDS * 4;
#pragma unroll
    for (int r = 0; r < 4; r++) {          // A: 128 rows x 8 x 16B
        int idx = r * 256 + tid;
        int row = idx >> 3, q = idx & 7;
        cpasync16(sa + (row * RSW + q * 4) * 4,
                  A + (size_t)(bm + row) * DM + k0 + q * 8);
    }
    uint32_t sb = sa + BM * RSW * 4;
#pragma unroll
    for (int r = 0; r < 8; r++) {          // B: 256 rows x 8 x 16B
        int idx = r * 256 + tid;
        int row = idx >> 3, q = idx & 7;
        cpasync16(sb + (row * RSW + q * 4) * 4,
                  W + (size_t)(bn + row) * DM + k0 + q * 8);
    }
    CP_COMMIT();
}

__global__ __launch_bounds__(256, 1)
void gemm_f16_kernel(const __half* __restrict__ A,
                     const __half* __restrict__ W,
                     const float* __restrict__ bias,
                     void* __restrict__ C0,
                     void* __restrict__ C1,
                     void* __restrict__ C2,
                     int outHalf)
{
    extern __shared__ uint32_t smw[];

    const int tid = threadIdx.x;
    const int bm = blockIdx.y * BM;
    const int bn = blockIdx.x * BN;
    const int wid = tid >> 5;
    const int lane = tid & 31;
    const int wm = wid >> 2;
    const int wn = wid & 3;
    const int g = lane >> 2;
    const int tg = lane & 3;
    uint32_t base = smem_u32(smw);

    float c[4][8][4];
#pragma unroll
    for (int i = 0; i < 4; i++)
#pragma unroll
        for (int j = 0; j < 8; j++)
#pragma unroll
            for (int v = 0; v < 4; v++) c[i][j][v] = 0.f;

#pragma unroll
    for (int s = 0; s < 3; s++)
        load_chunk_h(A, W, base, s, bm, bn, s * BKH, tid);

    const int NCHUNK = DM / BKH;    // 32
    for (int k = 0; k < NCHUNK; k++) {
        CP_WAIT(2);
        __syncthreads();
        if (k + 3 < NCHUNK)
            load_chunk_h(A, W, base, (k + 3) & 3, bm, bn, (k + 3) * BKH, tid);

        const uint32_t* As = smw + (k & 3) * STAGE_WORDS;
        const uint32_t* Bs = As + BM * RSW;

#pragma unroll
        for (int kw = 0; kw < 32; kw += 8) {   // four k16 steps (word offset)
            uint32_t a[4][4], b[8][2];
#pragma unroll
            for (int i = 0; i < 4; i++) {
                int w0 = (wm * 64 + i * 16 + g) * RSW + kw + tg;
                a[i][0] = As[w0];
                a[i][1] = As[w0 + 8 * RSW];
                a[i][2] = As[w0 + 4];
                a[i][3] = As[w0 + 8 * RSW + 4];
            }
#pragma unroll
            for (int j = 0; j < 8; j++) {
                int wb = (wn * 64 + j * 8 + g) * RSW + kw + tg;
                b[j][0] = Bs[wb];
                b[j][1] = Bs[wb + 4];
            }
#pragma unroll
            for (int i = 0; i < 4; i++)
#pragma unroll
                for (int j = 0; j < 8; j++)
                    mma_f16(c[i][j], a[i], b[j]);
        }
    }

    // Epilogue: select output buffer by which 2048-column block bn is in
    const int which = bn >> 11;
    void* Csel = (which == 0) ? C0 : ((which == 1) ? C1 : C2);

#pragma unroll
    for (int j = 0; j < 8; j++) {
        int col = bn + wn * 64 + j * 8 + 2 * tg;
        int coll = col & (DM - 1);
        float b0 = bias[col], b1 = bias[col + 1];
#pragma unroll
        for (int i = 0; i < 4; i++) {
            int row0 = bm + wm * 64 + i * 16 + g;
            float v00 = c[i][j][0] + b0, v01 = c[i][j][1] + b1;
            float v10 = c[i][j][2] + b0, v11 = c[i][j][3] + b1;
            if (outHalf) {
                __half* C = (__half*)Csel;
                __half2 h0 = __floats2half2_rn(v00, v01);
                __half2 h1 = __floats2half2_rn(v10, v11);
                *(__half2*)&C[(size_t)row0 * DM + coll] = h0;
                *(__half2*)&C[(size_t)(row0 + 8) * DM + coll] = h1;
            } else {
                float* C = (float*)Csel;
                *(float2*)&C[(size_t)row0 * DM + coll] = make_float2(v00, v01);
                *(float2*)&C[(size_t)(row0 + 8) * DM + coll] = make_float2(v10, v11);
            }
        }
    }
}

// ===========================================================================
// Tensor-core flash attention (fp16 mma.sync, fp32 softmax/accum).
// Unchanged from Round 5 (passing, near tensor floor).
// ===========================================================================
#define FQ 128
#define FK 64
#define QSW 68
#define PSW 36

#define OFF_Q  0
#define OFF_K  (FQ * QSW)
#define OFF_VT (OFF_K + FK * QSW)
#define OFF_P  (OFF_VT + HD * PSW)
#define OFF_MS (OFF_P + FQ * PSW)
#define FLASH_SMEM_BYTES ((OFF_MS + 64) * 4)

__global__ __launch_bounds__(256, 1)
void flash_f16_kernel(const __half* __restrict__ Q, const __half* __restrict__ K,
                      const __half* __restrict__ V, const int* __restrict__ mask,
                      __half* __restrict__ O)
{
    extern __shared__ uint32_t smw[];
    uint32_t* Qs = smw + OFF_Q;
    uint32_t* Ks = smw + OFF_K;
    uint32_t* Vt = smw + OFF_VT;
    uint32_t* Ps = smw + OFF_P;
    int*      msk = (int*)(smw + OFF_MS);
    __half*   VtH = (__half*)Vt;

    const int tid = threadIdx.x;
    const int wid = tid >> 5;
    const int lane = tid & 31;
    const int g = lane >> 2;
    const int tg = lane & 3;
    const int b = blockIdx.x >> 4;
    const int h = blockIdx.x & 15;
    const int q0 = blockIdx.y * FQ;
    const size_t base = (size_t)b * TS * DM + (size_t)h * HD;
    const float scale = 0.08838834764831845f;
    const int qr = wid * 16;

    for (int i = tid; i < FQ * (HD / 8); i += 256) {
        int r = i >> 4, c8 = i & 15;
        *(uint4*)&Qs[r * QSW + c8 * 4] =
            *(const uint4*)&Q[base + (size_t)(q0 + r) * DM + c8 * 8];
    }

    float m0 = -CUDART_INF_F, m1 = -CUDART_INF_F;
    float l0 = 0.f, l1 = 0.f;
    float co[16][4];
#pragma unroll
    for (int j = 0; j < 16; j++)
#pragma unroll
        for (int v = 0; v < 4; v++) co[j][v] = 0.f;

    for (int kt = 0; kt < TS / FK; kt++) {
        const int k0 = kt * FK;
        __syncthreads();

        for (int i = tid; i < FK * (HD / 8); i += 256) {
            int r = i >> 4, c8 = i & 15;
            *(uint4*)&Ks[r * QSW + c8 * 4] =
                *(const uint4*)&K[base + (size_t)(k0 + r) * DM + c8 * 8];
        }
        for (int i = tid; i < FK * (HD / 8); i += 256) {
            int r = i & 63, c8 = i >> 6;
            uint4 vv = *(const uint4*)&V[base + (size_t)(k0 + r) * DM + c8 * 8];
            const __half2* hp = (const __half2*)&vv;
            int c = c8 * 8;
#pragma unroll
            for (int t = 0; t < 4; t++) {
                VtH[(c + 2 * t + 0) * (2 * PSW) + r] = __low2half(hp[t]);
                VtH[(c + 2 * t + 1) * (2 * PSW) + r] = __high2half(hp[t]);
            }
        }
        if (tid < 64) msk[tid] = mask[b * TS + k0 + tid];
        __syncthreads();

        float cs[8][4];
#pragma unroll
        for (int j = 0; j < 8; j++)
#pragma unroll
            for (int v = 0; v < 4; v++) cs[j][v] = 0.f;

#pragma unroll
        for (int ks = 0; ks < 8; ks++) {
            int kw = ks * 8;
            uint32_t a[4];
            int ra = (qr + g) * QSW + kw + tg;
            a[0] = Qs[ra];
            a[1] = Qs[ra + 8 * QSW];
            a[2] = Qs[ra + 4];
            a[3] = Qs[ra + 8 * QSW + 4];
#pragma unroll
            for (int j = 0; j < 8; j++) {
                uint32_t bb[2];
                int rb = (j * 8 + g) * QSW + kw + tg;
                bb[0] = Ks[rb];
                bb[1] = Ks[rb + 4];
                mma_f16(cs[j], a, bb);
            }
        }

#pragma unroll
        for (int j = 0; j < 8; j++) {
            int c0 = j * 8 + 2 * tg;
            int mk0 = msk[c0], mk1 = msk[c0 + 1];
            cs[j][0] = mk0 ? cs[j][0] * scale : -CUDART_INF_F;
            cs[j][1] = mk1 ? cs[j][1] * scale : -CUDART_INF_F;
            cs[j][2] = mk0 ? cs[j][2] * scale : -CUDART_INF_F;
            cs[j][3] = mk1 ? cs[j][3] * scale : -CUDART_INF_F;
        }

        float mx0 = -CUDART_INF_F, mx1 = -CUDART_INF_F;
#pragma unroll
        for (int j = 0; j < 8; j++) {
            mx0 = fmaxf(mx0, fmaxf(cs[j][0], cs[j][1]));
            mx1 = fmaxf(mx1, fmaxf(cs[j][2], cs[j][3]));
        }
        mx0 = fmaxf(mx0, __shfl_xor_sync(0xffffffffu, mx0, 1));
        mx0 = fmaxf(mx0, __shfl_xor_sync(0xffffffffu, mx0, 2));
        mx1 = fmaxf(mx1, __shfl_xor_sync(0xffffffffu, mx1, 1));
        mx1 = fmaxf(mx1, __shfl_xor_sync(0xffffffffu, mx1, 2));

        float mn0 = fmaxf(m0, mx0), mn1 = fmaxf(m1, mx1);
        float corr0 = __expf(m0 - mn0), corr1 = __expf(m1 - mn1);
        m0 = mn0; m1 = mn1;

        float rs0 = 0.f, rs1 = 0.f;
#pragma unroll
        for (int j = 0; j < 8; j++) {
            __half2 h0 = __floats2half2_rn(__expf(cs[j][0] - mn0),
                                           __expf(cs[j][1] - mn0));
            __half2 h1 = __floats2half2_rn(__expf(cs[j][2] - mn1),
                                           __expf(cs[j][3] - mn1));
            float2 f0 = __half22float2(h0);
            float2 f1 = __half22float2(h1);
            rs0 += f0.x + f0.y; rs1 += f1.x + f1.y;
            int wp = j * 4 + tg;
            Ps[(qr + g) * PSW + wp] = *(uint32_t*)&h0;
            Ps[(qr + g + 8) * PSW + wp] = *(uint32_t*)&h1;
        }
        rs0 += __shfl_xor_sync(0xffffffffu, rs0, 1);
        rs0 += __shfl_xor_sync(0xffffffffu, rs0, 2);
        rs1 += __shfl_xor_sync(0xffffffffu, rs1, 1);
        rs1 += __shfl_xor_sync(0xffffffffu, rs1, 2);
        l0 = l0 * corr0 + rs0;
        l1 = l1 * corr1 + rs1;

#pragma unroll
        for (int j = 0; j < 16; j++) {
            co[j][0] *= corr0; co[j][1] *= corr0;
            co[j][2] *= corr1; co[j][3] *= corr1;
        }
        __syncwarp();

#pragma unroll
        for (int ks2 = 0; ks2 < 4; ks2++) {
            int kw = ks2 * 8;
            uint32_t a[4];
            int ra = (qr + g) * PSW + kw + tg;
            a[0] = Ps[ra];
            a[1] = Ps[ra + 8 * PSW];
            a[2] = Ps[ra + 4];
            a[3] = Ps[ra + 8 * PSW + 4];
#pragma unroll
            for (int j2 = 0; j2 < 16; j2++) {
                uint32_t bb[2];
                int rb = (j2 * 8 + g) * PSW + kw + tg;
                bb[0] = Vt[rb];
                bb[1] = Vt[rb + 4];
                mma_f16(co[j2], a, bb);
            }
        }
        __syncwarp();
    }

    float inv0 = 1.f / l0, inv1 = 1.f / l1;
    size_t r0 = (size_t)(q0 + qr + g);
    size_t r1 = r0 + 8;
#pragma unroll
    for (int j2 = 0; j2 < 16; j2++) {
        int col = j2 * 8 + 2 * tg;
        __half2 h0 = __floats2half2_rn(co[j2][0] * inv0, co[j2][1] * inv0);
        __half2 h1 = __floats2half2_rn(co[j2][2] * inv1, co[j2][3] * inv1);
        *(__half2*)&O[base + r0 * DM + col] = h0;
        *(__half2*)&O[base + r1 * DM + col] = h1;
    }
}

// ---------------------------------------------------------------------------
extern "C" void kernel_launch(void* const* d_in, const int* in_sizes, int n_in,
                              void* d_out, int out_size)
{
    const float* x  = (const float*)d_in[0];
    const int* mask = (const int*)d_in[1];
    const float* Wq = (const float*)d_in[2];
    const float* bq = (const float*)d_in[3];
    const float* Wk = (const float*)d_in[4];
    const float* bk = (const float*)d_in[5];
    const float* Wv = (const float*)d_in[6];
    const float* bv = (const float*)d_in[7];
    const float* Wo = (const float*)d_in[8];
    const float* bo = (const float*)d_in[9];
    float* out = (float*)d_out;

    __half *xh, *wh, *qh, *kh, *vh, *ah;
    float* bias3;
    cudaGetSymbolAddress((void**)&xh, g_xh);
    cudaGetSymbolAddress((void**)&wh, g_wh);
    cudaGetSymbolAddress((void**)&qh, g_qh);
    cudaGetSymbolAddress((void**)&kh, g_kh);
    cudaGetSymbolAddress((void**)&vh, g_vh);
    cudaGetSymbolAddress((void**)&ah, g_ah);
    cudaGetSymbolAddress((void**)&bias3, g_bias3);

    cudaFuncSetAttribute(gemm_f16_kernel,
                         cudaFuncAttributeMaxDynamicSharedMemorySize, GEMM_SMEM);
    cudaFuncSetAttribute(flash_f16_kernel,
                         cudaFuncAttributeMaxDynamicSharedMemorySize,
                         FLASH_SMEM_BYTES);

    const int NX4 = MR * DM / 4;
    const int NW4 = DM * DM / 4;

    // fp32 -> fp16 conversion (rne); bias concat
    cvt_f2h_kernel<<<1024, 256>>>(x,  xh, NX4);
    cvt_f2h_kernel<<<512,  256>>>(Wq, wh + 0 * (size_t)DM * DM, NW4);
    cvt_f2h_kernel<<<512,  256>>>(Wk, wh + 1 * (size_t)DM * DM, NW4);
    cvt_f2h_kernel<<<512,  256>>>(Wv, wh + 2 * (size_t)DM * DM, NW4);
    cvt_f2h_kernel<<<512,  256>>>(Wo, wh + 3 * (size_t)DM * DM, NW4);
    pack_bias_kernel<<<8, 256>>>(bq, bk, bv, bias3);

    // Fused QKV projection: N = 6144 over concatenated weights
    dim3 qkvgrid(NQKV / BN, MR / BM);  // (24, 64)
    gemm_f16_kernel<<<qkvgrid, 256, GEMM_SMEM>>>(
        xh, wh, bias3, qh, kh, vh, 1);

    flash_f16_kernel<<<dim3(NB * NHEADS, TS / FQ), 256, FLASH_SMEM_BYTES>>>(
        qh, kh, vh, mask, ah);

    // Final projection (float output)
    dim3 ogrid(DM / BN, MR / BM);      // (8, 64)
    gemm_f16_kernel<<<ogrid, 256, GEMM_SMEM>>>(
        ah, wh + 3 * (size_t)DM * DM, bo, out, nullptr, nullptr, 0);
}